// round 10
// baseline (speedup 1.0000x reference)
#include <cuda_runtime.h>
#include <cuda_bf16.h>
#include <cstdint>

#define NEVT 8192
#define NSEVT 16384
#define DIM 128

// ---------------- scratch (__device__ globals: no allocation allowed) -----
__device__ float g_sproj[NSEVT];                       // s_proj * log2(e)
__device__ float g_eproj[NEVT];                        // e_proj * log2(e)
// B (subevent^T) as e4m3 mma-fragments, per 64-k tile: 2048 uint32 (8KB)
//   idx = (((ks*2+half)*4 + p)*32 + lane)*4 + j
//   nb = p*2+(j>>1), reg = j&1;  n = half*64 + nb*8 + (lane>>2)
//   k  = ks*32 + reg*16 + (lane&3)*4 + byte
__device__ uint32_t g_BF[256 * 2048];                  // 2 MB
__device__ float g_num[2ull * NEVT * DIM];             // split-K numerator partials
__device__ float g_z[2 * NEVT];                        // split-K Z partials (x 2^-5)

// ---------------- helpers ---------------------------------------------------
__device__ __forceinline__ uint32_t smem_u32(const void* p) {
    uint32_t a;
    asm("{ .reg .u64 t; cvta.to.shared.u64 t, %1; cvt.u32.u64 %0, t; }"
        : "=r"(a) : "l"(p));
    return a;
}

__device__ __forceinline__ float ex2f(float x) {   // 2^x
    float y;
    asm("ex2.approx.ftz.f32 %0, %1;" : "=f"(y) : "f"(x));
    return y;
}

// pack 4 floats -> 4 e4m3 bytes (ascending)
__device__ __forceinline__ uint32_t pack_e4m3x4(float a, float b, float c, float d) {
    uint16_t lo, hi;
    asm("cvt.rn.satfinite.e4m3x2.f32 %0, %1, %2;" : "=h"(lo) : "f"(b), "f"(a));
    asm("cvt.rn.satfinite.e4m3x2.f32 %0, %1, %2;" : "=h"(hi) : "f"(d), "f"(c));
    return (uint32_t)lo | ((uint32_t)hi << 16);
}

__device__ __forceinline__ void mma_fp8(float* d, const uint32_t* a,
                                        uint32_t b0, uint32_t b1) {
    asm volatile(
        "mma.sync.aligned.m16n8k32.row.col.f32.e4m3.e4m3.f32 "
        "{%0,%1,%2,%3}, {%4,%5,%6,%7}, {%8,%9}, {%0,%1,%2,%3};"
        : "+f"(d[0]), "+f"(d[1]), "+f"(d[2]), "+f"(d[3])
        : "r"(a[0]), "r"(a[1]), "r"(a[2]), "r"(a[3]), "r"(b0), "r"(b1));
}

__device__ __forceinline__ void mbar_init(uint32_t a, uint32_t cnt) {
    asm volatile("mbarrier.init.shared.b64 [%0], %1;" :: "r"(a), "r"(cnt) : "memory");
}
__device__ __forceinline__ void mbar_arrive(uint32_t a) {
    asm volatile("mbarrier.arrive.shared.b64 _, [%0];" :: "r"(a) : "memory");
}
__device__ __forceinline__ void mbar_wait(uint32_t a, uint32_t parity) {
    asm volatile(
        "{\n\t.reg .pred P;\n\t"
        "WAITLP_%=:\n\t"
        "mbarrier.try_wait.parity.acquire.cta.shared::cta.b64 P, [%0], %1, 0x989680;\n\t"
        "@P bra.uni WAITDN_%=;\n\t"
        "bra.uni WAITLP_%=;\n\t"
        "WAITDN_%=:\n\t}"
        :: "r"(a), "r"(parity) : "memory");
}

__device__ __forceinline__ void cp_async16(uint32_t dst, const void* src) {
    asm volatile("cp.async.cg.shared.global [%0], [%1], 16;"
                 :: "r"(dst), "l"(src) : "memory");
}
__device__ __forceinline__ void cp_async_commit() {
    asm volatile("cp.async.commit_group;" ::: "memory");
}
__device__ __forceinline__ void cp_async_wait0() {
    asm volatile("cp.async.wait_group 0;" ::: "memory");
}

// ---------------- kernel 1: projections (scaled by log2 e) ------------------
__global__ void proj_kernel(const float* __restrict__ sub,
                            const float* __restrict__ evt,
                            const float* __restrict__ w) {
    const float L = 1.4426950408889634f;
    int gw = (blockIdx.x * blockDim.x + threadIdx.x) >> 5;
    int lane = threadIdx.x & 31;
    int nw = (gridDim.x * blockDim.x) >> 5;
    for (int r = gw; r < NSEVT + NEVT; r += nw) {
        const float* base;
        const float* wp;
        if (r < NSEVT) { base = sub + (size_t)r * DIM; wp = w; }
        else           { base = evt + (size_t)(r - NSEVT) * DIM; wp = w + DIM; }
        float4 v = ((const float4*)base)[lane];
        float4 ww = __ldg((const float4*)wp + lane);
        float d = v.x * ww.x + v.y * ww.y + v.z * ww.z + v.w * ww.w;
        #pragma unroll
        for (int o = 16; o; o >>= 1) d += __shfl_xor_sync(0xffffffffu, d, o);
        if (lane == 0) {
            if (r < NSEVT) g_sproj[r] = d * L;
            else           g_eproj[r - NSEVT] = d * L;
        }
    }
}

// ---------------- kernel 2: subevent -> e4m3 B-fragments --------------------
__global__ void bfrag_kernel(const float* __restrict__ sub) {
    __shared__ float smf[64][132];          // padded rows
    const int t = threadIdx.x;              // 256 threads
    const int kt = blockIdx.x;              // 0..255 (global 64-k tile)
    const int jl = t >> 2;                  // row 0..63
    const int cb = t & 3;
    const float4* src = (const float4*)(sub + (size_t)(kt * 64 + jl) * DIM);
    #pragma unroll
    for (int it = 0; it < 8; ++it) {
        float4 v = src[cb + it * 4];
        int d = (cb + it * 4) * 4;
        smf[jl][d + 0] = v.x; smf[jl][d + 1] = v.y;
        smf[jl][d + 2] = v.z; smf[jl][d + 3] = v.w;
    }
    __syncthreads();
    uint32_t* dst = g_BF + (size_t)kt * 2048;
    #pragma unroll
    for (int i = 0; i < 8; ++i) {
        int idx = t + i * 256;
        int j = idx & 3, lane = (idx >> 2) & 31, p = (idx >> 7) & 3;
        int half = (idx >> 9) & 1, ks = idx >> 10;
        int n = half * 64 + (p * 2 + (j >> 1)) * 8 + (lane >> 2);
        int kb = ks * 32 + (j & 1) * 16 + (lane & 3) * 4;
        dst[idx] = pack_e4m3x4(smf[kb][n], smf[kb + 1][n], smf[kb + 2][n], smf[kb + 3][n]);
    }
}

// ---------------- kernel 3: warp-specialized fused softmax-GEMM (fp8) -------
// grid 128 (64 row-tiles x 2 k-halves), 512 threads.
// warps 0-7: consumers (LDS.128 fragments + mma fp8 m16n8k32).
// warps 8-15: producers (coalesced adj stream, exp2(t-5), fragment STS, Z).
// smem: [0,32768) sproj; [32768,+128) mbarriers; stages of 16KB (A 8KB + B 8KB)
#define SP_OFF   0
#define BAR_OFF  32768
#define ST_OFF   33024
#define A_SZ     8192
#define STAGE_SZ 16384
#define NSTAGE   8
#define SMEM_BYTES (ST_OFF + NSTAGE * STAGE_SZ)

__global__ void __launch_bounds__(512, 1)
main_kernel(const float* __restrict__ adj) {
    extern __shared__ char smem[];
    const int tid = threadIdx.x;
    const int wid = tid >> 5;
    const int lid = tid & 31;

    const int tile = blockIdx.x >> 1;
    const int kv_half = blockIdx.x & 1;
    const int i0 = tile * 128;
    const int k0 = kv_half * (NSEVT / 2);

    const uint32_t sb = smem_u32(smem);

    // cooperative sproj load (all 512 threads)
    {
        float4* spd = (float4*)(smem + SP_OFF);
        const float4* sps = (const float4*)(g_sproj + k0);
        for (int i = tid; i < 2048; i += 512) spd[i] = __ldg(sps + i);
    }
    if (tid == 0) {
        #pragma unroll
        for (int s = 0; s < NSTAGE; ++s) {
            mbar_init(sb + BAR_OFF + s * 16, 256);      // full[s]
            mbar_init(sb + BAR_OFF + s * 16 + 8, 256);  // empty[s]
        }
    }
    __syncthreads();

    if (wid >= 8) {
        // =================== PRODUCER ===================
        const int pw = wid - 8;          // 0..7
        const int ptid = tid - 256;      // 0..255
        const int h = lid >> 4;          // half-warp
        const int c4 = lid & 15;         // float4 column slot within 64-col tile
        const int rbase = pw * 2 + h;    // row for i=0 (rows: i*16+rbase)

        const float4* a4p = (const float4*)(adj + (size_t)(i0 + rbase) * NSEVT + k0) + c4;
        const char* bfbase = (const char*)g_BF + (size_t)(kv_half * 128) * 8192 + ptid * 32;
        const float4* sp4 = (const float4*)(smem + SP_OFF);

        float epArr[8];
        float zrow[8];
        #pragma unroll
        for (int i = 0; i < 8; ++i) {
            epArr[i] = g_eproj[i0 + i * 16 + rbase];
            zrow[i] = 0.f;
        }

        // A fragment store address (fixed per thread, +i*1024 per row group)
        const uint32_t lane_a = (uint32_t)(rbase & 7) * 4u + (uint32_t)(c4 & 3);
        const uint32_t rsel = ((uint32_t)(c4 >> 2) & 1u) * 2u + ((uint32_t)(rbase >> 3) & 1u);
        const uint32_t ast = ((uint32_t)(c4 >> 3)) * 512u + lane_a * 16u + rsel * 4u;
        const uint32_t bst = (uint32_t)ptid * 32u;

        float4 areg[8];
        #pragma unroll
        for (int i = 0; i < 8; ++i) areg[i] = __ldg(a4p + (size_t)i * 65536);

        int st = 0, ph = 1;

        for (int kt = 0; kt < 128; ++kt) {
            float4 s = sp4[kt * 16 + c4];

            // exp2(adj*f(c) - 5) : W scaled by 2^-5 (Z scaled identically -> cancels)
            uint32_t wpk[8];
            #pragma unroll
            for (int i = 0; i < 8; ++i) {
                float4 a = areg[i];
                float ep = epArr[i];
                float c0 = ep + s.x, c1 = ep + s.y, c2 = ep + s.z, c3 = ep + s.w;
                float f0 = fmaxf(c0, 0.2f * c0), f1 = fmaxf(c1, 0.2f * c1);
                float f2 = fmaxf(c2, 0.2f * c2), f3 = fmaxf(c3, 0.2f * c3);
                float e0 = ex2f(fmaf(a.x, f0, -5.0f));
                float e1 = ex2f(fmaf(a.y, f1, -5.0f));
                float e2 = ex2f(fmaf(a.z, f2, -5.0f));
                float e3 = ex2f(fmaf(a.w, f3, -5.0f));
                zrow[i] += (e0 + e1) + (e2 + e3);
                wpk[i] = pack_e4m3x4(e0 * a.x, e1 * a.y, e2 * a.z, e3 * a.w);
            }

            // prefetch next adj tile
            if (kt < 127) {
                const float4* anext = a4p + (kt + 1) * 16;
                #pragma unroll
                for (int i = 0; i < 8; ++i) areg[i] = __ldg(anext + (size_t)i * 65536);
            }

            mbar_wait(sb + BAR_OFF + st * 16 + 8, ph);   // empty[st]

            const uint32_t stg = sb + ST_OFF + (uint32_t)st * STAGE_SZ;
            // B fragments: gmem -> smem via cp.async (32B/thread)
            {
                const char* bsrc = bfbase + (size_t)kt * 8192;
                cp_async16(stg + A_SZ + bst, bsrc);
                cp_async16(stg + A_SZ + bst + 16, bsrc + 16);
                cp_async_commit();
            }
            // A fragment stores (one uint32 per row-group)
            {
                char* Ab = smem + (stg - sb);
                #pragma unroll
                for (int i = 0; i < 8; ++i)
                    *reinterpret_cast<uint32_t*>(Ab + ast + i * 1024) = wpk[i];
            }
            cp_async_wait0();
            mbar_arrive(sb + BAR_OFF + st * 16);         // full[st]

            if (++st == NSTAGE) { st = 0; ph ^= 1; }
        }

        // Z: reduce across 16-lane column groups
        #pragma unroll
        for (int i = 0; i < 8; ++i) {
            float z = zrow[i];
            z += __shfl_xor_sync(0xffffffffu, z, 8);
            z += __shfl_xor_sync(0xffffffffu, z, 4);
            z += __shfl_xor_sync(0xffffffffu, z, 2);
            z += __shfl_xor_sync(0xffffffffu, z, 1);
            if (c4 == 0)
                g_z[(size_t)kv_half * NEVT + i0 + i * 16 + rbase] = z;
        }

    } else {
        // =================== CONSUMER ===================
        const int mwarp = wid & 3;
        const int nhalf = wid >> 2;
        const int m0 = mwarp * 32;
        const int n0 = nhalf * 64;

        float acc[2][8][4];
        #pragma unroll
        for (int mt = 0; mt < 2; ++mt)
            #pragma unroll
            for (int nb = 0; nb < 8; ++nb)
                #pragma unroll
                for (int q = 0; q < 4; ++q) acc[mt][nb][q] = 0.f;

        int st = 0, ph = 0;

        for (int kt = 0; kt < 128; ++kt) {
            mbar_wait(sb + BAR_OFF + st * 16, ph);   // full[st]

            const char* Asm = smem + ST_OFF + (size_t)st * STAGE_SZ;
            const char* Bsm = Asm + A_SZ;
            #pragma unroll
            for (int ks = 0; ks < 2; ++ks) {
                uint4 A0 = *reinterpret_cast<const uint4*>(
                    Asm + (mwarp * 4 + ks) * 512 + lid * 16);
                uint4 A1 = *reinterpret_cast<const uint4*>(
                    Asm + (mwarp * 4 + 2 + ks) * 512 + lid * 16);
                uint4 Bq[4];
                #pragma unroll
                for (int p = 0; p < 4; ++p)
                    Bq[p] = *reinterpret_cast<const uint4*>(
                        Bsm + ((ks * 2 + nhalf) * 4 + p) * 512 + lid * 16);

                uint32_t af0[4] = {A0.x, A0.y, A0.z, A0.w};
                uint32_t af1[4] = {A1.x, A1.y, A1.z, A1.w};
                #pragma unroll
                for (int p = 0; p < 4; ++p) {
                    mma_fp8(acc[0][2 * p],     af0, Bq[p].x, Bq[p].y);
                    mma_fp8(acc[0][2 * p + 1], af0, Bq[p].z, Bq[p].w);
                    mma_fp8(acc[1][2 * p],     af1, Bq[p].x, Bq[p].y);
                    mma_fp8(acc[1][2 * p + 1], af1, Bq[p].z, Bq[p].w);
                }
            }

            mbar_arrive(sb + BAR_OFF + st * 16 + 8);  // empty[st]
            if (++st == NSTAGE) { st = 0; ph ^= 1; }
        }

        // numerator partial writeout (scaled by 2^-5, cancels with Z)
        float* base = g_num + (size_t)kv_half * NEVT * DIM;
        const int r01 = i0 + m0 + (lid >> 2);
        const int colb = n0 + (lid & 3) * 2;
        #pragma unroll
        for (int mt = 0; mt < 2; ++mt) {
            #pragma unroll
            for (int nb = 0; nb < 8; ++nb) {
                int rr = r01 + mt * 16;
                int cc = colb + nb * 8;
                float2 lo = make_float2(acc[mt][nb][0], acc[mt][nb][1]);
                float2 hi = make_float2(acc[mt][nb][2], acc[mt][nb][3]);
                *reinterpret_cast<float2*>(base + (size_t)rr * DIM + cc) = lo;
                *reinterpret_cast<float2*>(base + (size_t)(rr + 8) * DIM + cc) = hi;
            }
        }
    }
}

// ---------------- kernel 4: combine split-K + epilogue ----------------------
__global__ void finalize_kernel(const float* __restrict__ evt, float* __restrict__ out) {
    int idx = blockIdx.x * blockDim.x + threadIdx.x;   // float4 index
    if (idx >= NEVT * (DIM / 4)) return;
    int i = idx >> 5;                                   // row
    float z = g_z[i] + g_z[NEVT + i];
    float inv = 1.0f / z;
    float4 n0 = *((const float4*)g_num + idx);
    float4 n1 = *((const float4*)g_num + (size_t)NEVT * (DIM / 4) + idx);
    float4 e = __ldg((const float4*)evt + idx);
    float4 o;
    o.x = (e.x + (n0.x + n1.x) * inv) * 0.5f;
    o.y = (e.y + (n0.y + n1.y) * inv) * 0.5f;
    o.z = (e.z + (n0.z + n1.z) * inv) * 0.5f;
    o.w = (e.w + (n0.w + n1.w) * inv) * 0.5f;
    ((float4*)out)[idx] = o;
}

// ---------------- launch ----------------------------------------------------
extern "C" void kernel_launch(void* const* d_in, const int* in_sizes, int n_in,
                              void* d_out, int out_size) {
    const float *adj = nullptr, *sub = nullptr, *evt = nullptr, *w = nullptr;
    for (int i = 0; i < n_in; ++i) {
        switch (in_sizes[i]) {
            case NEVT * NSEVT: adj = (const float*)d_in[i]; break;
            case NSEVT * DIM:  sub = (const float*)d_in[i]; break;
            case NEVT * DIM:   evt = (const float*)d_in[i]; break;
            case 2 * DIM:      w   = (const float*)d_in[i]; break;
            default: break;
        }
    }
    (void)out_size;

    static int configured = 0;
    if (!configured) {
        cudaFuncSetAttribute(main_kernel, cudaFuncAttributeMaxDynamicSharedMemorySize,
                             SMEM_BYTES);
        configured = 1;
    }

    proj_kernel<<<96, 256>>>(sub, evt, w);
    bfrag_kernel<<<256, 256>>>(sub);
    main_kernel<<<128, 512, SMEM_BYTES>>>(adj);
    finalize_kernel<<<(NEVT * (DIM / 4) + 255) / 256, 256>>>(evt, (float*)d_out);
}